// round 6
// baseline (speedup 1.0000x reference)
#include <cuda_runtime.h>

typedef unsigned long long u64;

// ---- packed f32x2 helpers (Blackwell sm_100+: add/mul/fma .f32x2 via PTX) ----
__device__ __forceinline__ u64 pk2(float lo, float hi) {
    u64 r;
    asm("mov.b64 %0, {%1, %2};" : "=l"(r) : "f"(lo), "f"(hi));
    return r;
}
__device__ __forceinline__ void upk2(u64 a, float& lo, float& hi) {
    asm("mov.b64 {%0, %1}, %2;" : "=f"(lo), "=f"(hi) : "l"(a));
}
__device__ __forceinline__ u64 fma2(u64 a, u64 b, u64 c) {
    u64 d;
    asm("fma.rn.f32x2 %0, %1, %2, %3;" : "=l"(d) : "l"(a), "l"(b), "l"(c));
    return d;
}
__device__ __forceinline__ u64 mul2(u64 a, u64 b) {
    u64 d;
    asm("mul.rn.f32x2 %0, %1, %2;" : "=l"(d) : "l"(a), "l"(b));
    return d;
}
__device__ __forceinline__ u64 add2(u64 a, u64 b) {
    u64 d;
    asm("add.rn.f32x2 %0, %1, %2;" : "=l"(d) : "l"(a), "l"(b));
    return d;
}
// exact negation via sign-bit flip -> ALU pipe (LOP3), keeps fma pipe free
__device__ __forceinline__ u64 neg2(u64 a) { return a ^ 0x8000000080000000ULL; }

// State layout: index b in [0,64), qubit w lives at bit (5-w)  (qubit 0 = MSB,
// matching the reference's C-order (2,)*6 tensor with axis w+1 = qubit w).
// Initial state after RX encodings: amp(b) = (-i)^k * P(b), k = popcount of
// encoded bits. Real gates thereafter => track (u,v) packed in one b64 reg.
__global__ void __launch_bounds__(128) qsim6_kernel(
    const float* __restrict__ x,
    const float* __restrict__ W,
    const float* __restrict__ ab,
    float* __restrict__ out,
    int nlayers, int B)
{
    int gid = blockIdx.x * blockDim.x + threadIdx.x;
    if (gid >= B) return;

    float4 xv = reinterpret_cast<const float4*>(x)[gid];
    float c0, s0, c1, s1, c2, s2, c3, s3;
    __sincosf(0.5f * xv.x, &s0, &c0);
    __sincosf(0.5f * xv.y, &s1, &c1);
    __sincosf(0.5f * xv.z, &s2, &c2);
    __sincosf(0.5f * xv.w, &s3, &c3);
    float ca0, sa0, ca1, sa1;
    __sincosf(0.5f * ab[0], &sa0, &ca0);
    __sincosf(0.5f * ab[1], &sa1, &ca1);

    // t4[i] = product over the 4 encoded qubits (bit3 of i = qubit0, ... bit0 = qubit3)
    float f0[2] = {c0, s0}, f1[2] = {c1, s1}, f2[2] = {c2, s2}, f3[2] = {c3, s3};
    float t2[4], t3[8], t4[16];
#pragma unroll
    for (int a = 0; a < 2; a++)
#pragma unroll
        for (int b = 0; b < 2; b++) t2[a * 2 + b] = f0[a] * f1[b];
#pragma unroll
    for (int a = 0; a < 4; a++)
#pragma unroll
        for (int b = 0; b < 2; b++) t3[a * 2 + b] = t2[a] * f2[b];
#pragma unroll
    for (int a = 0; a < 8; a++)
#pragma unroll
        for (int b = 0; b < 2; b++) t4[a * 2 + b] = t3[a] * f3[b];

    // ancilla (qubit4 = bit1 of j, qubit5 = bit0 of j) after RY(ancilla_bias): |0> -> (cos, sin)
    float anc[4] = {ca0 * ca1, ca0 * sa1, sa0 * ca1, sa0 * sa1};

    u64 S[64];
#pragma unroll
    for (int b = 0; b < 64; b++) {
        const int i = b >> 2, j = b & 3;
        float P = t4[i] * anc[j];
        const int k = ((i >> 3) & 1) + ((i >> 2) & 1) + ((i >> 1) & 1) + (i & 1);
        const int km = k & 3;                        // (-i)^k phase
        if (km == 0)      S[b] = pk2(P, 0.0f);       //  +real
        else if (km == 1) S[b] = pk2(0.0f, -P);      //  -i
        else if (km == 2) S[b] = pk2(-P, 0.0f);      //  -1
        else              S[b] = pk2(0.0f, P);       //  +i
    }

    for (int l = 0; l < nlayers; l++) {
        // CNOT ring: control w -> target (w+1)%6, applied sequentially
#pragma unroll
        for (int w = 0; w < 6; w++) {
            const int cm = 1 << (5 - w);
            const int tm = 1 << (5 - ((w + 1) % 6));
#pragma unroll
            for (int b = 0; b < 64; b++) {
                if ((b & cm) && !(b & tm)) {
                    u64 t = S[b]; S[b] = S[b | tm]; S[b | tm] = t;
                }
            }
        }
        // RY(weights[l][w]) on each qubit: [c -s; s c], same real op on u and v
#pragma unroll
        for (int w = 0; w < 6; w++) {
            float s, c;
            __sincosf(0.5f * __ldg(&W[l * 6 + w]), &s, &c);
            const u64 cc = pk2(c, c);
            const u64 ss = pk2(s, s);
            const u64 ns = neg2(ss);
            const int m = 1 << (5 - w);
#pragma unroll
            for (int b = 0; b < 64; b++) {
                if (!(b & m)) {
                    u64 a0 = S[b], a1 = S[b | m];
                    S[b]     = fma2(ns, a1, mul2(cc, a0));   // c*a0 - s*a1
                    S[b | m] = fma2(ss, a0, mul2(cc, a1));   // s*a0 + c*a1
                }
            }
        }
    }

    // p_b = u_b^2 + v_b^2 (kept packed); marginalize the two ancilla qubits first
    u64 m16[16];
#pragma unroll
    for (int i = 0; i < 16; i++) {
        u64 acc = mul2(S[4 * i], S[4 * i]);
        acc = fma2(S[4 * i + 1], S[4 * i + 1], acc);
        acc = fma2(S[4 * i + 2], S[4 * i + 2], acc);
        acc = fma2(S[4 * i + 3], S[4 * i + 3], acc);
        m16[i] = acc;
    }
    // <Z_w> = sum_i sign_w(i) * m16[i]; qubit0 -> bit3 of i, ..., qubit3 -> bit0
    u64 A0 = m16[0], A1 = m16[0], A2 = m16[0], A3 = m16[0];
#pragma unroll
    for (int i = 1; i < 16; i++) {
        const u64 mi = m16[i];
        const u64 ni = neg2(mi);
        A0 = add2(A0, (i & 8) ? ni : mi);
        A1 = add2(A1, (i & 4) ? ni : mi);
        A2 = add2(A2, (i & 2) ? ni : mi);
        A3 = add2(A3, (i & 1) ? ni : mi);
    }

    float lo, hi;
    float4 o;
    upk2(A0, lo, hi); o.x = lo + hi;   // u^2 part + v^2 part
    upk2(A1, lo, hi); o.y = lo + hi;
    upk2(A2, lo, hi); o.z = lo + hi;
    upk2(A3, lo, hi); o.w = lo + hi;
    reinterpret_cast<float4*>(out)[gid] = o;
}

extern "C" void kernel_launch(void* const* d_in, const int* in_sizes, int n_in,
                              void* d_out, int out_size) {
    const float* x  = (const float*)d_in[0];   // (B, 4)
    const float* W  = (const float*)d_in[1];   // (NL, 6)
    const float* ab = (const float*)d_in[2];   // (2,)
    float* out = (float*)d_out;                // (B, 4)
    const int B = in_sizes[0] / 4;
    const int nlayers = in_sizes[1] / 6;
    const int threads = 128;
    const int blocks = (B + threads - 1) / threads;
    qsim6_kernel<<<blocks, threads>>>(x, W, ab, out, nlayers, B);
}

// round 7
// speedup vs baseline: 1.1628x; 1.1628x over previous
#include <cuda_runtime.h>

typedef unsigned long long u64;

// ---- packed f32x2 helpers ----
__device__ __forceinline__ u64 fma2(u64 a, u64 b, u64 c) {
    u64 d;
    asm("fma.rn.f32x2 %0, %1, %2, %3;" : "=l"(d) : "l"(a), "l"(b), "l"(c));
    return d;
}
__device__ __forceinline__ void upk2(u64 a, float& lo, float& hi) {
    asm("mov.b64 {%0, %1}, %2;" : "=f"(lo), "=f"(hi) : "l"(a));
}

__host__ __device__ constexpr int pc4(int t) {
    return (t & 1) + ((t >> 1) & 1) + ((t >> 2) & 1) + ((t >> 3) & 1);
}
__host__ __device__ constexpr bool inc_pair(int t, int t2) {
    return ((pc4(t) ^ pc4(t2)) & 1) == 0;
}

// compact slot of included pair (t<=t2) in (t outer asc, t2 inner asc) order
__device__ int pair_index(int t, int t2) {
    int k = 0;
    for (int a = 0; a < 16; a++)
        for (int b = a; b < 16; b++) {
            if (a == t && b == t2) return k;
            if (inc_pair(a, b)) k++;
        }
    return -1;
}

static const int NPAIR = 72;  // pairs (t<=t2) with equal popcount parity
__device__ float4 g_Ck[NPAIR];

// ---------------------------------------------------------------------------
// Prep kernel (1 block, 256 threads): propagate the 16 real basis columns
// through the fixed circuit (CNOT ring + RY layers), then bake the quadratic-
// form coefficient table  C_w[t,t2] = chi * (t==t2?1:2) * sum_b s_w(b) M_t[b] M_t2[b]
// ---------------------------------------------------------------------------
__global__ void prep_kernel(const float* __restrict__ W,
                            const float* __restrict__ ab, int nlayers) {
    __shared__ float M[16][65];  // padded: avoid bank conflicts in reduction
    const int tid = threadIdx.x;

    if (tid < 16) {
        float ca0, sa0, ca1, sa1;
        __sincosf(0.5f * ab[0], &sa0, &ca0);
        __sincosf(0.5f * ab[1], &sa1, &ca1);
        float A[4] = {ca0 * ca1, ca0 * sa1, sa0 * ca1, sa0 * sa1};

        float r[64];
#pragma unroll
        for (int b = 0; b < 64; b++) r[b] = ((b >> 2) == tid) ? A[b & 3] : 0.0f;

        for (int l = 0; l < nlayers; l++) {
#pragma unroll
            for (int w = 0; w < 6; w++) {
                const int cm = 1 << (5 - w);
                const int tm = 1 << (5 - ((w + 1) % 6));
#pragma unroll
                for (int b = 0; b < 64; b++) {
                    if ((b & cm) && !(b & tm)) {
                        float t = r[b]; r[b] = r[b | tm]; r[b | tm] = t;
                    }
                }
            }
#pragma unroll
            for (int w = 0; w < 6; w++) {
                float s, c;
                __sincosf(0.5f * W[l * 6 + w], &s, &c);
                const int m = 1 << (5 - w);
#pragma unroll
                for (int b = 0; b < 64; b++) {
                    if (!(b & m)) {
                        float a0 = r[b], a1 = r[b | m];
                        r[b]     = fmaf(c, a0, -s * a1);
                        r[b | m] = fmaf(s, a0,  c * a1);
                    }
                }
            }
        }
#pragma unroll
        for (int b = 0; b < 64; b++) M[tid][b] = r[b];
    }
    __syncthreads();

    const int t = tid >> 4, t2 = tid & 15;
    if (t <= t2 && inc_pair(t, t2)) {
        float a0 = 0.f, a1 = 0.f, a2 = 0.f, a3 = 0.f;
#pragma unroll
        for (int b = 0; b < 64; b++) {
            float pr = M[t][b] * M[t2][b];
            a0 += ((b >> 5) & 1) ? -pr : pr;  // qubit 0 sign
            a1 += ((b >> 4) & 1) ? -pr : pr;  // qubit 1
            a2 += ((b >> 3) & 1) ? -pr : pr;  // qubit 2
            a3 += ((b >> 2) & 1) ? -pr : pr;  // qubit 3
        }
        // chi = Re(phase_t * conj(phase_t2)), phase = (-i)^popc; same parity
        const int pt = pc4(t), pt2 = pc4(t2);
        float f = ((((pt - pt2) & 3) == 0) ? 1.0f : -1.0f) * ((t == t2) ? 1.0f : 2.0f);
        g_Ck[pair_index(t, t2)] = make_float4(f * a0, f * a1, f * a2, f * a3);
    }
}

// ---------------------------------------------------------------------------
// Main kernel: per sample, T(x) (16 products of encoding cos/sin), then
// out_w = sum over 72 pairs of C_w[k] * T[t]*T[t2], packed 2 outputs per fma2.
// ---------------------------------------------------------------------------
__global__ void __launch_bounds__(256) qmain_kernel(
    const float* __restrict__ x, float* __restrict__ out, int B)
{
    __shared__ float4 sC[NPAIR];
    if (threadIdx.x < NPAIR) sC[threadIdx.x] = g_Ck[threadIdx.x];
    __syncthreads();

    const int gid = blockIdx.x * blockDim.x + threadIdx.x;
    if (gid >= B) return;

    float4 xv = reinterpret_cast<const float4*>(x)[gid];
    float c0, s0, c1, s1, c2, s2, c3, s3;
    __sincosf(0.5f * xv.x, &s0, &c0);
    __sincosf(0.5f * xv.y, &s1, &c1);
    __sincosf(0.5f * xv.z, &s2, &c2);
    __sincosf(0.5f * xv.w, &s3, &c3);

    // T[t]: bit3 of t = qubit0 (c0/s0), ..., bit0 = qubit3
    float f0[2] = {c0, s0}, f1[2] = {c1, s1}, f2[2] = {c2, s2}, f3[2] = {c3, s3};
    float t2a[4], t3a[8], T[16];
#pragma unroll
    for (int a = 0; a < 2; a++)
#pragma unroll
        for (int b = 0; b < 2; b++) t2a[a * 2 + b] = f0[a] * f1[b];
#pragma unroll
    for (int a = 0; a < 4; a++)
#pragma unroll
        for (int b = 0; b < 2; b++) t3a[a * 2 + b] = t2a[a] * f2[b];
#pragma unroll
    for (int a = 0; a < 8; a++)
#pragma unroll
        for (int b = 0; b < 2; b++) T[a * 2 + b] = t3a[a] * f3[b];

    u64 acc01 = 0ULL, acc23 = 0ULL;  // bits of (0.0f, 0.0f)
    int k = 0;  // constant-folded after full unroll
#pragma unroll
    for (int t = 0; t < 16; t++) {
#pragma unroll
        for (int tb = t; tb < 16; tb++) {
            if (inc_pair(t, tb)) {   // compile-time: popcount parity filter
                float p = T[t] * T[tb];
                ulonglong2 cc = *reinterpret_cast<const ulonglong2*>(&sC[k]);
                u64 p2;
                asm("mov.b64 %0, {%1, %1};" : "=l"(p2) : "f"(p));
                acc01 = fma2(cc.x, p2, acc01);
                acc23 = fma2(cc.y, p2, acc23);
                k++;
            }
        }
    }

    float4 o;
    upk2(acc01, o.x, o.y);
    upk2(acc23, o.z, o.w);
    reinterpret_cast<float4*>(out)[gid] = o;
}

extern "C" void kernel_launch(void* const* d_in, const int* in_sizes, int n_in,
                              void* d_out, int out_size) {
    const float* x  = (const float*)d_in[0];   // (B, 4)
    const float* W  = (const float*)d_in[1];   // (NL, 6)
    const float* ab = (const float*)d_in[2];   // (2,)
    float* out = (float*)d_out;                // (B, 4)
    const int B = in_sizes[0] / 4;
    const int nlayers = in_sizes[1] / 6;

    prep_kernel<<<1, 256>>>(W, ab, nlayers);

    const int threads = 256;
    const int blocks = (B + threads - 1) / threads;
    qmain_kernel<<<blocks, threads>>>(x, out, B);
}

// round 8
// speedup vs baseline: 1.4337x; 1.2330x over previous
#include <cuda_runtime.h>

typedef unsigned long long u64;
static const unsigned FULL = 0xFFFFFFFFu;

// ---- packed f32x2 helpers ----
__device__ __forceinline__ u64 pk2(float lo, float hi) {
    u64 r;
    asm("mov.b64 %0, {%1, %2};" : "=l"(r) : "f"(lo), "f"(hi));
    return r;
}
__device__ __forceinline__ void upk2(u64 a, float& lo, float& hi) {
    asm("mov.b64 {%0, %1}, %2;" : "=f"(lo), "=f"(hi) : "l"(a));
}
__device__ __forceinline__ u64 fma2(u64 a, u64 b, u64 c) {
    u64 d;
    asm("fma.rn.f32x2 %0, %1, %2, %3;" : "=l"(d) : "l"(a), "l"(b), "l"(c));
    return d;
}
__device__ __forceinline__ u64 mul2(u64 a, u64 b) {
    u64 d;
    asm("mul.rn.f32x2 %0, %1, %2;" : "=l"(d) : "l"(a), "l"(b));
    return d;
}

__host__ __device__ constexpr int PC4(int t) {
    return (t & 1) + ((t >> 1) & 1) + ((t >> 2) & 1) + ((t >> 3) & 1);
}
__host__ __device__ constexpr int PC3(int a) {
    return (a & 1) + ((a >> 1) & 1) + ((a >> 2) & 1);
}

// group index helpers (must match main loop enumeration order: a asc, b asc)
__device__ int e_index(int a, int b) {
    int k = 0;
    for (int aa = 0; aa < 8; aa++)
        for (int bb = aa + 1; bb < 8; bb++)
            if (((PC3(aa) ^ PC3(bb)) & 1) == 0) {
                if (aa == a && bb == b) return k;
                k++;
            }
    return 0;
}
__device__ int o_index(int a, int b) {
    int k = 0;
    for (int aa = 0; aa < 8; aa++)
        for (int bb = aa + 1; bb < 8; bb++)
            if (((PC3(aa) ^ PC3(bb)) & 1) == 1) {
                if (aa == a && bb == b) return k;
                k++;
            }
    return 0;
}

// ---------------------------------------------------------------------------
// Fused kernel, 512 threads/block, one sample per thread.
// Phase 1 (prep, all 16 warps): warp t propagates real basis column t through
//   the fixed circuit using warp shuffles (2 amps/lane: b = (lane<<1)|r,
//   lane bit (4-w) = qubit w for w<=4, r = qubit5 bit).
// Phase 2 (256 threads): bake quadratic-form coefficients into the grouped
//   packed table sC[36][8]  (36 groups x 4 outputs x (lo,hi)).
// Phase 3 (all threads): per-sample T products + 36 packed group FMAs.
// ---------------------------------------------------------------------------
__global__ void __launch_bounds__(512) qfused_kernel(
    const float* __restrict__ x,
    const float* __restrict__ W,
    const float* __restrict__ ab,
    float* __restrict__ out,
    int nlayers, int B)
{
    __shared__ float sM[16][65];
    __shared__ __align__(16) float sC[36 * 8];

    const int tid = threadIdx.x;
    const int lane = tid & 31;
    const int wp = tid >> 5;  // warp id = basis column index t (bit3 = qubit0)
    const int gid = blockIdx.x * 512 + tid;

    // issue the sample load early; latency hides under prep
    float4 xv = make_float4(0.f, 0.f, 0.f, 0.f);
    if (gid < B) xv = reinterpret_cast<const float4*>(x)[gid];

    // ---------------- Phase 1: shuffle-based column propagation ----------------
    {
        float ca0, sa0, ca1, sa1;
        __sincosf(0.5f * __ldg(&ab[0]), &sa0, &ca0);
        __sincosf(0.5f * __ldg(&ab[1]), &sa1, &ca1);
        // ancilla amp A[(q4<<1)|q5]
        float Ae0 = ca0 * ca1, Ae1 = ca0 * sa1;  // q4=0
        float Ao0 = sa0 * ca1, Ao1 = sa0 * sa1;  // q4=1
        const bool hit = ((lane >> 1) == wp);    // lane bits 4..1 = qubits 0..3
        float r0, r1;
        if (lane & 1) { r0 = hit ? Ao0 : 0.f; r1 = hit ? Ao1 : 0.f; }
        else          { r0 = hit ? Ae0 : 0.f; r1 = hit ? Ae1 : 0.f; }

        for (int l = 0; l < nlayers; l++) {
            // CNOT ring: (0,1)(1,2)(2,3)(3,4) in lane bits
#pragma unroll
            for (int w = 0; w < 4; w++) {
                const int cm = 16 >> w, tm = 8 >> w;
                float t0 = __shfl_xor_sync(FULL, r0, tm);
                float t1 = __shfl_xor_sync(FULL, r1, tm);
                if (lane & cm) { r0 = t0; r1 = t1; }
            }
            // (4,5): control lane bit0, target in-register
            if (lane & 1) { float t = r0; r0 = r1; r1 = t; }
            // (5,0): control r-index, target lane bit4
            r1 = __shfl_xor_sync(FULL, r1, 16);
            // RY on qubits 0..4 (lane bits), then qubit 5 (in-register)
#pragma unroll
            for (int w = 0; w < 5; w++) {
                float s, c;
                __sincosf(0.5f * __ldg(&W[l * 6 + w]), &s, &c);
                const int m = 16 >> w;
                float o0 = __shfl_xor_sync(FULL, r0, m);
                float o1 = __shfl_xor_sync(FULL, r1, m);
                float sg = (lane & m) ? s : -s;
                r0 = fmaf(sg, o0, c * r0);
                r1 = fmaf(sg, o1, c * r1);
            }
            {
                float s, c;
                __sincosf(0.5f * __ldg(&W[l * 6 + 5]), &s, &c);
                float n0 = fmaf(-s, r1, c * r0);
                float n1 = fmaf(s, r0, c * r1);
                r0 = n0; r1 = n1;
            }
        }
        sM[wp][2 * lane]     = r0;  // b bit0 = qubit5
        sM[wp][2 * lane + 1] = r1;
    }
    __syncthreads();

    // ---------------- Phase 2: coefficient table ----------------
    if (tid < 256) {
        const int t = tid >> 4, tb = tid & 15;
        if (t <= tb && (((PC4(t) ^ PC4(tb)) & 1) == 0)) {
            float a0 = 0.f, a1 = 0.f, a2 = 0.f, a3 = 0.f;
#pragma unroll
            for (int b = 0; b < 64; b++) {
                float pr = sM[t][b] * sM[tb][b];
                a0 += (b & 32) ? -pr : pr;  // qubit 0
                a1 += (b & 16) ? -pr : pr;  // qubit 1
                a2 += (b & 8)  ? -pr : pr;  // qubit 2
                a3 += (b & 4)  ? -pr : pr;  // qubit 3
            }
            const int d = (PC4(t) - PC4(tb)) & 3;  // chi = +1 (d==0) / -1 (d==2)
            const float f = (d == 0 ? 1.f : -1.f) * (t == tb ? 1.f : 2.f);
            const int a = t >> 1, i = t & 1, b2 = tb >> 1, jj = tb & 1;
            int j, slot;
            if (a == b2)      { j = a;                    slot = i; }  // diag group
            else if (i == jj) { j = 8 + e_index(a, b2);   slot = i; }  // E group
            else              { j = 20 + o_index(a, b2);  slot = i; }  // O group
            sC[j * 8 + 0 + slot] = f * a0;
            sC[j * 8 + 2 + slot] = f * a1;
            sC[j * 8 + 4 + slot] = f * a2;
            sC[j * 8 + 6 + slot] = f * a3;
        }
    }
    __syncthreads();

    // ---------------- Phase 3: per-sample quadratic form ----------------
    if (gid >= B) return;

    float c0, s0, c1, s1, c2, s2, c3, s3;
    __sincosf(0.5f * xv.x, &s0, &c0);
    __sincosf(0.5f * xv.y, &s1, &c1);
    __sincosf(0.5f * xv.z, &s2, &c2);
    __sincosf(0.5f * xv.w, &s3, &c3);

    // t3a[a]: a bit2 = qubit0 factor, bit1 = qubit1, bit0 = qubit2
    float f0[2] = {c0, s0}, f1[2] = {c1, s1}, f2[2] = {c2, s2};
    float t2a[4], t3a[8];
#pragma unroll
    for (int a = 0; a < 2; a++)
#pragma unroll
        for (int b = 0; b < 2; b++) t2a[a * 2 + b] = f0[a] * f1[b];
#pragma unroll
    for (int a = 0; a < 4; a++)
#pragma unroll
        for (int b = 0; b < 2; b++) t3a[a * 2 + b] = t2a[a] * f2[b];

    const u64 cs3 = pk2(c3, s3);
    const u64 sc3 = pk2(s3, c3);
    u64 Tp[8], Ts[8];  // Tp[a] = (T[2a], T[2a+1]),  Ts[a] = swapped
#pragma unroll
    for (int a = 0; a < 8; a++) {
        u64 dd = pk2(t3a[a], t3a[a]);
        Tp[a] = mul2(dd, cs3);
        Ts[a] = mul2(dd, sc3);
    }

    u64 acc0 = 0ULL, acc1 = 0ULL, acc2 = 0ULL, acc3 = 0ULL;

#define ACCUM(J, PP) do {                                                     \
        u64 pp_ = (PP);                                                       \
        const ulonglong2* q_ = reinterpret_cast<const ulonglong2*>(&sC[(J) * 8]); \
        ulonglong2 qa_ = q_[0], qb_ = q_[1];                                  \
        acc0 = fma2(qa_.x, pp_, acc0);                                        \
        acc1 = fma2(qa_.y, pp_, acc1);                                        \
        acc2 = fma2(qb_.x, pp_, acc2);                                        \
        acc3 = fma2(qb_.y, pp_, acc3);                                        \
    } while (0)

    // diag groups j = 0..7:  (T2a^2, T2a+1^2)
#pragma unroll
    for (int a = 0; a < 8; a++) ACCUM(a, mul2(Tp[a], Tp[a]));
    // E groups j = 8..19: (T2a*T2b, T2a+1*T2b+1), same pc3 parity
    {
        int j = 8;
#pragma unroll
        for (int a = 0; a < 8; a++)
#pragma unroll
            for (int b = a + 1; b < 8; b++)
                if (((PC3(a) ^ PC3(b)) & 1) == 0) { ACCUM(j, mul2(Tp[a], Tp[b])); j++; }
    }
    // O groups j = 20..35: (T2a*T2b+1, T2a+1*T2b), different pc3 parity
    {
        int j = 20;
#pragma unroll
        for (int a = 0; a < 8; a++)
#pragma unroll
            for (int b = a + 1; b < 8; b++)
                if (((PC3(a) ^ PC3(b)) & 1) == 1) { ACCUM(j, mul2(Tp[a], Ts[b])); j++; }
    }
#undef ACCUM

    float lo, hi;
    float4 o;
    upk2(acc0, lo, hi); o.x = lo + hi;
    upk2(acc1, lo, hi); o.y = lo + hi;
    upk2(acc2, lo, hi); o.z = lo + hi;
    upk2(acc3, lo, hi); o.w = lo + hi;
    reinterpret_cast<float4*>(out)[gid] = o;
}

extern "C" void kernel_launch(void* const* d_in, const int* in_sizes, int n_in,
                              void* d_out, int out_size) {
    const float* x  = (const float*)d_in[0];   // (B, 4)
    const float* W  = (const float*)d_in[1];   // (NL, 6)
    const float* ab = (const float*)d_in[2];   // (2,)
    float* out = (float*)d_out;                // (B, 4)
    const int B = in_sizes[0] / 4;
    const int nlayers = in_sizes[1] / 6;
    const int threads = 512;
    const int blocks = (B + threads - 1) / threads;
    qfused_kernel<<<blocks, threads>>>(x, W, ab, out, nlayers, B);
}